// round 17
// baseline (speedup 1.0000x reference)
#include <cuda_runtime.h>

#define NA    25
#define NHW   1444
#define NV    361         // float4 per field-plane
#define PLV   1805        // float4 per anchor (5 fields)
#define NT    192
#define H0CNT 181
#define H1CNT 180
#define FSTR  182         // smem field stride (float4)
#define STG4  (5 * FSTR)
#define GRID  888         // persistent blocks (6 per SM x 148)
#define BMAX  512

__constant__ float c_bw[5] = {1.3221f, 3.19275f, 5.05587f, 9.47112f, 11.2364f};
__constant__ float c_bh[5] = {1.73145f, 4.00944f, 8.09892f, 4.84053f, 10.0071f};
__constant__ float c_sc[5] = {0.5f, 0.75f, 1.0f, 1.25f, 1.5f};

struct BP {
    float gl, gr, gt, gb, garea;
    float txt, tyt, twt, tht;
    int   sidx, best;
};

__device__ __align__(16) float g_part[GRID];
__device__ unsigned g_done = 0;

__device__ __forceinline__ float tanhapx(float x) {
    float t; asm("tanh.approx.f32 %0, %1;" : "=f"(t) : "f"(x)); return t;
}
__device__ __forceinline__ float ex2apx(float x) {
    float t; asm("ex2.approx.f32 %0, %1;" : "=f"(t) : "f"(x)); return t;
}
__device__ __forceinline__ float lg2apx(float x) {
    float t; asm("lg2.approx.f32 %0, %1;" : "=f"(t) : "f"(x)); return t;
}
__device__ __forceinline__ unsigned atomic_inc_release(unsigned* p) {
    unsigned old;
    asm volatile("atom.release.gpu.add.u32 %0, [%1], %2;"
                 : "=r"(old) : "l"(p), "r"(1u) : "memory");
    return old;
}
__device__ __forceinline__ void cp_async16(void* sdst, const void* gsrc) {
    unsigned saddr = (unsigned)__cvta_generic_to_shared(sdst);
    asm volatile("cp.async.cg.shared.global [%0], [%1], 16;"
                 :: "r"(saddr), "l"(gsrc));
}
__device__ __forceinline__ void cp_commit() {
    asm volatile("cp.async.commit_group;");
}
template<int N> __device__ __forceinline__ void cp_wait() {
    asm volatile("cp.async.wait_group %0;" :: "n"(N));
}

struct ACC { float A, B, C; };

__device__ __forceinline__ void cell_hot(
    float tx, float ty, float tw, float th, float tc,
    float fw, float fh, float lhw, float lhh,
    float gl, float gr, float gt, float gb, float garea, ACC& acc)
{
    const float L2E = 1.4426950408889634f;
    float tX = tanhapx(0.5f * tx);
    float tY = tanhapx(0.5f * ty);
    float tC = tanhapx(0.5f * tc);
    float bx = fmaf(tX, 0.5f, fw);
    float by = fmaf(tY, 0.5f, fh);
    float hw = ex2apx(fmaf(tw, L2E, lhw));
    float hh = ex2apx(fmaf(th, L2E, lhh));
    float rx = fminf(bx + hw, gr);
    float lx = fmaxf(bx - hw, gl);
    float ry = fminf(by + hh, gb);
    float ly = fmaxf(by - hh, gt);
    float cw = fmaxf(rx - lx, 0.0f);
    float ch = fmaxf(ry - ly, 0.0f);
    float inter = cw * ch;
    float uni   = fmaf(hw * hh, 4.0f, garea) - inter;
    bool noobj  = fmaf(uni, -0.6f, inter) <= 0.0f;
    float pc  = fmaf(tC, 0.5f, 0.5f);
    float pcm = noobj ? pc : 0.0f;
    acc.A = fmaf(tX, tX, acc.A);
    acc.A = fmaf(tY, tY, acc.A);
    acc.B = fmaf(tw, tw, acc.B);
    acc.B = fmaf(th, th, acc.B);
    acc.C = fmaf(pcm, pcm, acc.C);
}

struct CO { float dense, inter, uni, sx, sy, pc; };
__device__ __forceinline__ CO cell_full(
    float tx, float ty, float tw, float th, float tc,
    float fw, float fh, float lhw, float lhh,
    float gl, float gr, float gt, float gb, float garea)
{
    const float L2E = 1.4426950408889634f;
    float tX = tanhapx(0.5f * tx);
    float tY = tanhapx(0.5f * ty);
    float tC = tanhapx(0.5f * tc);
    float bx = fmaf(tX, 0.5f, fw);
    float by = fmaf(tY, 0.5f, fh);
    float hw = ex2apx(fmaf(tw, L2E, lhw));
    float hh = ex2apx(fmaf(th, L2E, lhh));
    float rx = fminf(bx + hw, gr);
    float lx = fmaxf(bx - hw, gl);
    float ry = fminf(by + hh, gb);
    float ly = fmaxf(by - hh, gt);
    float cw = fmaxf(rx - lx, 0.0f);
    float ch = fmaxf(ry - ly, 0.0f);
    float inter = cw * ch;
    float uni   = fmaf(hw * hh, 4.0f, garea) - inter;
    bool noobj  = fmaf(uni, -0.6f, inter) <= 0.0f;
    float pc  = fmaf(tC, 0.5f, 0.5f);
    float pcm = noobj ? pc : 0.0f;
    CO o;
    o.dense = 0.125f * fmaf(tX, tX, tY * tY)
            + 0.5f   * fmaf(tw, tw, th * th)
            + 0.5f   * (pcm * pcm);
    o.inter = inter; o.uni = uni;
    o.sx = fmaf(tX, 0.5f, 0.5f);
    o.sy = fmaf(tY, 0.5f, 0.5f);
    o.pc = pc;
    return o;
}

__device__ __forceinline__ const float4* tile_base4(const float4* pred4, int t) {
    int b = t / 5;
    int g = t - b * 5;
    return pred4 + (size_t)(b * 25 + g * 5) * PLV;
}

// issue cp.async for one stage (anchor j, half h). Thread v copies exactly
// the smem slots thread v will later read -> buffers are thread-private.
__device__ __forceinline__ void stage_load(
    float4* sdst, const float4* __restrict__ p4, int j, int h, int tid)
{
    const float4* gsrc = p4 + j * PLV + h * H0CNT;
    const int cnt = h ? H1CNT : H0CNT;
    if (tid < cnt) {
#pragma unroll
        for (int f = 0; f < 5; f++)
            cp_async16(sdst + f * FSTR + tid, gsrc + f * NV + tid);
    }
}

__device__ __forceinline__ void compute_bp_into(
    const float* __restrict__ tgt, int b, BP* dst)
{
    float gx = tgt[4 * b + 0] * 38.0f;
    float gy = tgt[4 * b + 1] * 38.0f;
    float gw = tgt[4 * b + 2] * 38.0f;
    float gh = tgt[4 * b + 3] * 38.0f;
    int gi = (int)gx;
    int gj = (int)gy;
    float garea = gw * gh;

    int best = 0;
    float binter = 0.0f, buni = 1.0f;
#pragma unroll
    for (int ai = 0; ai < NA; ai++) {
        float aw = c_bw[ai % 5] * c_sc[ai / 5];
        float ah = c_bh[ai % 5] * c_sc[ai / 5];
        float in_ = fminf(aw, gw) * fminf(ah, gh);
        float un  = aw * ah + garea - in_;
        if (ai == 0 || in_ * buni > binter * un) {
            binter = in_; buni = un; best = ai;
        }
    }
    float baw = c_bw[best % 5] * c_sc[best / 5];
    float bah = c_bh[best % 5] * c_sc[best / 5];

    const float LN2 = 0.6931471805599453f;
    dst->gl = gx - 0.5f * gw;  dst->gr = gx + 0.5f * gw;
    dst->gt = gy - 0.5f * gh;  dst->gb = gy + 0.5f * gh;
    dst->garea = garea;
    dst->txt = gx - (float)gi;
    dst->tyt = gy - (float)gj;
    dst->twt = (lg2apx(gw) - lg2apx(baw)) * LN2;
    dst->tht = (lg2apx(gh) - lg2apx(bah)) * LN2;
    dst->sidx = gj * 38 + gi;
    dst->best = best;
}

__global__ void __launch_bounds__(NT) main_kernel(
    const float* __restrict__ pred, const float* __restrict__ tgt,
    float* __restrict__ out, int ntt)   // ntt = total tiles = 5*B
{
    const int bid = blockIdx.x;
    const int G = gridDim.x;

    __shared__ __align__(16) float4 sbuf[2][STG4];   // 29,120 B double buffer
    __shared__ BP sbp[2];
    __shared__ float ws[6];
    __shared__ bool isLast;

    const float4* pred4 = (const float4*)pred;
    const int v = threadIdx.x;

    const int ntiles = (bid < ntt) ? ((ntt - 1 - bid) / G + 1) : 0;
    const int totalStages = ntiles * 10;

    // ---- prime: load stage 0 of first tile; thread0 computes its BP ----
    int tL = bid;                       // load-cursor tile
    const float4* pL = (ntiles > 0) ? tile_base4(pred4, bid) : pred4;
    if (ntiles > 0) stage_load(sbuf[0], pL, 0, 0, v);
    cp_commit();
    int sL = 1;                         // next stage within tile tL to load
    if (v == 0 && ntiles > 0) compute_bp_into(tgt, bid / 5, &sbp[0]);
    __syncthreads();

    ACC acc; acc.A = 0.0f; acc.B = 0.0f; acc.C = 0.0f;
    float corr = 0.0f;
    int i = 0;                          // global stage counter (buffer parity)

    for (int k = 0; k < ntiles; k++) {
        const int tC = bid + k * G;
        const int gC = tC - (tC / 5) * 5;
        const float sc = c_sc[gC];

        // hoist this tile's BP (sbp[k&1]) to registers; safe: tile-boundary
        // barrier of the previous iteration ordered thread0's write.
        const BP bpv = sbp[k & 1];
        const float gl = bpv.gl, gr = bpv.gr, gt_ = bpv.gt, gb = bpv.gb;
        const float garea = bpv.garea;

        for (int s = 0; s < 10; s++, i++) {
            // issue next stage's copy (flat stream, crosses tile boundary)
            if (i + 1 < totalStages) {
                if (sL == 10) { sL = 0; tL += G; pL = tile_base4(pred4, tL); }
                stage_load(sbuf[(i + 1) & 1], pL, sL >> 1, sL & 1, v);
                cp_commit();
                sL++;
                cp_wait<1>();           // this thread's stage-i data ready
            } else {
                cp_wait<0>();
            }
            // NO barrier: smem slots are thread-private (loader == consumer)

            const int j = s >> 1, h = s & 1;
            const int cnt = h ? H1CNT : H0CNT;
            const float lhw = __log2f(0.5f * c_bw[j] * sc);
            const float lhh = __log2f(0.5f * c_bh[j] * sc);

            if (v < cnt) {
                const float4* sb = sbuf[i & 1];
                float4 X = sb[v];
                float4 Y = sb[v + FSTR];
                float4 W = sb[v + 2 * FSTR];
                float4 H = sb[v + 3 * FSTR];
                float4 C = sb[v + 4 * FSTR];
                float xa[4] = {X.x, X.y, X.z, X.w};
                float ya[4] = {Y.x, Y.y, Y.z, Y.w};
                float wa[4] = {W.x, W.y, W.z, W.w};
                float ha[4] = {H.x, H.y, H.z, H.w};
                float ca[4] = {C.x, C.y, C.z, C.w};
                int base = 4 * (h * H0CNT + v);
                int h0 = (base * 1725) >> 16;
                int w0 = base - h0 * 38;
                float w0f = (float)w0 + 0.5f;
                float h0f = (float)h0 + 0.5f;
#pragma unroll
                for (int kk = 0; kk < 4; kk++) {
                    float fw = w0f + (float)kk;
                    float fh = h0f;
                    if (fw > 38.0f) { fw -= 38.0f; fh += 1.0f; }
                    cell_hot(xa[kk], ya[kk], wa[kk], ha[kk], ca[kk],
                             fw, fh, lhw, lhh, gl, gr, gt_, gb, garea, acc);
                }
            }

            // thread0 side jobs (overlapped; published by tile barrier)
            if (v == 0 && s == 0 && k + 1 < ntiles)
                compute_bp_into(tgt, (bid + (k + 1) * G) / 5, &sbp[(k + 1) & 1]);

            if (v == 0 && s == 9 && bpv.best >= gC * 5 && bpv.best < gC * 5 + 5) {
                int jj = bpv.best - gC * 5;
                int idx = bpv.sidx;
                const float* p = (const float*)(tile_base4(pred4, tC) + jj * PLV);
                float tx = __ldg(p + idx);
                float ty = __ldg(p + idx + NHW);
                float tw = __ldg(p + idx + 2 * NHW);
                float th = __ldg(p + idx + 3 * NHW);
                float tc = __ldg(p + idx + 4 * NHW);
                float clhw = __log2f(0.5f * c_bw[jj] * sc);
                float clhh = __log2f(0.5f * c_bh[jj] * sc);
                int hh_ = (idx * 1725) >> 16;
                int ww_ = idx - hh_ * 38;
                CO o = cell_full(tx, ty, tw, th, tc,
                                 (float)ww_ + 0.5f, (float)hh_ + 0.5f,
                                 clhw, clhh, gl, gr, gt_, gb, garea);
                float dx = o.sx - bpv.txt;
                float dy = o.sy - bpv.tyt;
                float dw = tw - bpv.twt;
                float dh = th - bpv.tht;
                float tconf = o.inter / o.uni;
                float dc = o.pc - tconf;
                float truec = 0.5f * (dx * dx + dy * dy + dw * dw + dh * dh)
                            + 2.5f * (dc * dc);
                corr += truec - o.dense;
            }
        }
        __syncthreads();   // tile boundary: publish next BP, bound warp drift
    }

    float part = fmaf(0.125f, acc.A, fmaf(0.5f, acc.B, 0.5f * acc.C)) + corr;

    // deterministic block reduction (6 warps)
#pragma unroll
    for (int off = 16; off > 0; off >>= 1)
        part += __shfl_down_sync(0xffffffffu, part, off);
    if ((v & 31) == 0) ws[v >> 5] = part;
    __syncthreads();
    if (v == 0) {
        float blocksum = ((ws[0] + ws[1]) + (ws[2] + ws[3])) + (ws[4] + ws[5]);
        g_part[bid] = blocksum;
        unsigned t = atomic_inc_release(&g_done);
        isLast = (t == (unsigned)(G - 1));
    }
    __syncthreads();

    if (isLast) {
        if (v == 0) {
            g_done = 0;
            __threadfence();
        }
        __syncthreads();
        __shared__ double sh[NT];
        const float4* __restrict__ pp = (const float4*)g_part;
        int n4 = G >> 2;                 // 222
        double s = 0.0;
        for (int ii = v; ii < n4; ii += NT) {
            float4 vv = __ldcg(pp + ii);
            s += ((double)vv.x + (double)vv.y) + ((double)vv.z + (double)vv.w);
        }
        sh[v] = s;
        __syncthreads();
        if (v < 64) sh[v] += sh[v + 128];
        __syncthreads();
#pragma unroll
        for (int off = 64; off > 0; off >>= 1) {
            if (v < off) sh[v] += sh[v + off];
            __syncthreads();
        }
        if (v == 0) out[0] = (float)sh[0];
    }
}

extern "C" void kernel_launch(void* const* d_in, const int* in_sizes, int n_in,
                              void* d_out, int out_size) {
    const float* pred = (const float*)d_in[0];
    const float* tgt  = (const float*)d_in[1];
    int B = in_sizes[1] / 4;
    if (B > BMAX) B = BMAX;

    main_kernel<<<GRID, NT>>>(pred, tgt, (float*)d_out, B * 5);
}